// round 2
// baseline (speedup 1.0000x reference)
#include <cuda_runtime.h>

#define NE 8
#define HID 2048
#define INT_DIM 2048
#define NTOK 4096
#define TK 8192         // NTOK * TOP_K
#define N1 4096         // 2 * INT_DIM

// ---------------- scratch (static device globals; no allocation) ----------------
__device__ int   d_off[NE + 1];
__device__ int   d_row_token[TK];     // sorted row -> token index
__device__ int   d_row_of_slot[TK];   // slot (t*2+k) -> sorted row
__device__ float d_gu  [(size_t)TK * N1];      // gate|up pre-activation, 134 MB
__device__ float d_act [(size_t)TK * INT_DIM]; // swiglu activations,      67 MB
__device__ float d_down[(size_t)TK * HID];     // down-proj per row,       67 MB

// ---------------- routing: group expanded slots by expert ----------------
__global__ void route_kernel(const int* __restrict__ topk) {
    __shared__ int s_cnt[NE];
    __shared__ int s_pos[NE];
    int tid = threadIdx.x;
    if (tid < NE) s_cnt[tid] = 0;
    __syncthreads();
    for (int s = tid; s < TK; s += blockDim.x)
        atomicAdd(&s_cnt[topk[s]], 1);
    __syncthreads();
    if (tid == 0) {
        int a = 0;
        for (int e = 0; e < NE; e++) { d_off[e] = a; s_pos[e] = a; a += s_cnt[e]; }
        d_off[NE] = a;
    }
    __syncthreads();
    for (int s = tid; s < TK; s += blockDim.x) {
        int e = topk[s];
        int r = atomicAdd(&s_pos[e], 1);
        d_row_token[r]   = s >> 1;
        d_row_of_slot[s] = r;
    }
}

// ---------------- GEMM1: gu[r, n] = sum_k hidden[token(r), k] * W_e[n, k] ----------------
// 128x128 tile, BK=8, 256 threads, 8x8 microtile per thread.
__global__ __launch_bounds__(256) void gemm1_kernel(
    const float* __restrict__ hidden, const float* __restrict__ gup) {
    const int e   = blockIdx.z;
    const int off = d_off[e];
    const int cnt = d_off[e + 1] - off;
    const int rt  = blockIdx.y * 128;
    if (rt >= cnt) return;
    const int nt = blockIdx.x * 128;
    const float* W = gup + (size_t)e * N1 * HID;

    __shared__ float As[8][132];
    __shared__ float Bs[8][132];

    const int tid = threadIdx.x;
    const int lr  = tid >> 1;        // 0..127
    const int lk  = (tid & 1) * 4;   // 0 or 4
    const int tx  = tid & 15;
    const int ty  = tid >> 4;

    const int  arow   = rt + lr;
    const bool avalid = arow < cnt;
    const float* aptr = nullptr;
    if (avalid) {
        int tok = d_row_token[off + arow];
        aptr = hidden + (size_t)tok * HID + lk;
    }
    const float* bptr = W + (size_t)(nt + lr) * HID + lk;

    float acc[8][8];
    #pragma unroll
    for (int i = 0; i < 8; i++)
        #pragma unroll
        for (int j = 0; j < 8; j++) acc[i][j] = 0.f;

    for (int k0 = 0; k0 < HID; k0 += 8) {
        float4 av = avalid ? *(const float4*)(aptr + k0) : make_float4(0.f, 0.f, 0.f, 0.f);
        float4 bv = *(const float4*)(bptr + k0);
        __syncthreads();
        As[lk + 0][lr] = av.x; As[lk + 1][lr] = av.y; As[lk + 2][lr] = av.z; As[lk + 3][lr] = av.w;
        Bs[lk + 0][lr] = bv.x; Bs[lk + 1][lr] = bv.y; Bs[lk + 2][lr] = bv.z; Bs[lk + 3][lr] = bv.w;
        __syncthreads();
        #pragma unroll
        for (int k = 0; k < 8; k++) {
            float4 a0 = *(const float4*)&As[k][ty * 8];
            float4 a1 = *(const float4*)&As[k][ty * 8 + 4];
            float4 b0 = *(const float4*)&Bs[k][tx * 8];
            float4 b1 = *(const float4*)&Bs[k][tx * 8 + 4];
            float a[8] = {a0.x, a0.y, a0.z, a0.w, a1.x, a1.y, a1.z, a1.w};
            float b[8] = {b0.x, b0.y, b0.z, b0.w, b1.x, b1.y, b1.z, b1.w};
            #pragma unroll
            for (int i = 0; i < 8; i++)
                #pragma unroll
                for (int j = 0; j < 8; j++)
                    acc[i][j] = fmaf(a[i], b[j], acc[i][j]);
        }
    }

    #pragma unroll
    for (int i = 0; i < 8; i++) {
        int row = rt + ty * 8 + i;
        if (row < cnt) {
            float* c = d_gu + (size_t)(off + row) * N1 + nt + tx * 8;
            *(float4*)(c)     = make_float4(acc[i][0], acc[i][1], acc[i][2], acc[i][3]);
            *(float4*)(c + 4) = make_float4(acc[i][4], acc[i][5], acc[i][6], acc[i][7]);
        }
    }
}

// ---------------- SwiGLU activation ----------------
__global__ void act_kernel() {
    size_t idx  = (size_t)blockIdx.x * blockDim.x + threadIdx.x;
    size_t base = idx * 4;
    if (base >= (size_t)TK * INT_DIM) return;
    int r = (int)(base / INT_DIM);
    int c = (int)(base % INT_DIM);
    const float* grow = d_gu + (size_t)r * N1;
    float4 g = *(const float4*)(grow + c);
    float4 u = *(const float4*)(grow + INT_DIM + c);
    float4 o;
    o.x = (g.x / (1.f + expf(-g.x))) * u.x;
    o.y = (g.y / (1.f + expf(-g.y))) * u.y;
    o.z = (g.z / (1.f + expf(-g.z))) * u.z;
    o.w = (g.w / (1.f + expf(-g.w))) * u.w;
    *(float4*)(d_act + (size_t)r * INT_DIM + c) = o;
}

// ---------------- GEMM2: down[r, n] = sum_k act[r, k] * Wd_e[n, k] ----------------
__global__ __launch_bounds__(256) void gemm2_kernel(const float* __restrict__ downW) {
    const int e   = blockIdx.z;
    const int off = d_off[e];
    const int cnt = d_off[e + 1] - off;
    const int rt  = blockIdx.y * 128;
    if (rt >= cnt) return;
    const int nt = blockIdx.x * 128;
    const float* W = downW + (size_t)e * HID * INT_DIM;

    __shared__ float As[8][132];
    __shared__ float Bs[8][132];

    const int tid = threadIdx.x;
    const int lr  = tid >> 1;
    const int lk  = (tid & 1) * 4;
    const int tx  = tid & 15;
    const int ty  = tid >> 4;

    const int  arow   = rt + lr;
    const bool avalid = arow < cnt;
    const float* aptr = avalid ? (d_act + (size_t)(off + arow) * INT_DIM + lk) : nullptr;
    const float* bptr = W + (size_t)(nt + lr) * INT_DIM + lk;

    float acc[8][8];
    #pragma unroll
    for (int i = 0; i < 8; i++)
        #pragma unroll
        for (int j = 0; j < 8; j++) acc[i][j] = 0.f;

    for (int k0 = 0; k0 < INT_DIM; k0 += 8) {
        float4 av = avalid ? *(const float4*)(aptr + k0) : make_float4(0.f, 0.f, 0.f, 0.f);
        float4 bv = *(const float4*)(bptr + k0);
        __syncthreads();
        As[lk + 0][lr] = av.x; As[lk + 1][lr] = av.y; As[lk + 2][lr] = av.z; As[lk + 3][lr] = av.w;
        Bs[lk + 0][lr] = bv.x; Bs[lk + 1][lr] = bv.y; Bs[lk + 2][lr] = bv.z; Bs[lk + 3][lr] = bv.w;
        __syncthreads();
        #pragma unroll
        for (int k = 0; k < 8; k++) {
            float4 a0 = *(const float4*)&As[k][ty * 8];
            float4 a1 = *(const float4*)&As[k][ty * 8 + 4];
            float4 b0 = *(const float4*)&Bs[k][tx * 8];
            float4 b1 = *(const float4*)&Bs[k][tx * 8 + 4];
            float a[8] = {a0.x, a0.y, a0.z, a0.w, a1.x, a1.y, a1.z, a1.w};
            float b[8] = {b0.x, b0.y, b0.z, b0.w, b1.x, b1.y, b1.z, b1.w};
            #pragma unroll
            for (int i = 0; i < 8; i++)
                #pragma unroll
                for (int j = 0; j < 8; j++)
                    acc[i][j] = fmaf(a[i], b[j], acc[i][j]);
        }
    }

    #pragma unroll
    for (int i = 0; i < 8; i++) {
        int row = rt + ty * 8 + i;
        if (row < cnt) {
            float* c = d_down + (size_t)(off + row) * HID + nt + tx * 8;
            *(float4*)(c)     = make_float4(acc[i][0], acc[i][1], acc[i][2], acc[i][3]);
            *(float4*)(c + 4) = make_float4(acc[i][4], acc[i][5], acc[i][6], acc[i][7]);
        }
    }
}

// ---------------- combine: out[t] = w0 * down[row(2t)] + w1 * down[row(2t+1)] ----------------
__global__ void combine_kernel(const float* __restrict__ wts, float* __restrict__ out) {
    size_t idx  = (size_t)blockIdx.x * blockDim.x + threadIdx.x;
    size_t base = idx * 4;
    if (base >= (size_t)NTOK * HID) return;
    int t = (int)(base / HID);
    int h = (int)(base % HID);
    int r0 = d_row_of_slot[2 * t];
    int r1 = d_row_of_slot[2 * t + 1];
    float w0 = wts[2 * t];
    float w1 = wts[2 * t + 1];
    float4 x0 = *(const float4*)(d_down + (size_t)r0 * HID + h);
    float4 x1 = *(const float4*)(d_down + (size_t)r1 * HID + h);
    float4 o;
    o.x = w0 * x0.x + w1 * x1.x;
    o.y = w0 * x0.y + w1 * x1.y;
    o.z = w0 * x0.z + w1 * x1.z;
    o.w = w0 * x0.w + w1 * x1.w;
    *(float4*)(out + base) = o;
}

// ---------------- launcher ----------------
extern "C" void kernel_launch(void* const* d_in, const int* in_sizes, int n_in,
                              void* d_out, int out_size) {
    const float* hidden = (const float*)d_in[0];
    const int*   topk   = (const int*)  d_in[1];
    const float* wts    = (const float*)d_in[2];
    const float* gup    = (const float*)d_in[3];
    const float* downW  = (const float*)d_in[4];
    float* out = (float*)d_out;

    route_kernel<<<1, 256>>>(topk);
    gemm1_kernel<<<dim3(N1 / 128, TK / 128, NE), 256>>>(hidden, gup);
    {
        size_t elems = (size_t)TK * INT_DIM / 4;
        act_kernel<<<(unsigned)((elems + 255) / 256), 256>>>();
    }
    gemm2_kernel<<<dim3(HID / 128, TK / 128, NE), 256>>>(downW);
    {
        size_t elems = (size_t)NTOK * HID / 4;
        combine_kernel<<<(unsigned)((elems + 255) / 256), 256>>>(wts, out);
    }
}

// round 5
// speedup vs baseline: 3.6363x; 3.6363x over previous
#include <cuda_runtime.h>
#include <cuda_fp16.h>
#include <cstdint>

#define NE 8
#define HID 2048
#define INT_DIM 2048
#define NTOK 4096
#define TK 8192
#define N1 4096

#define BK 32            // k-floats per tile
#define LDS_H 40         // halves per smem row (32 data + 8 pad = 80B, conflict-free)
#define TILE_HALVES (128 * LDS_H)

// ---------------- scratch ----------------
__device__ int    d_off[NE + 1];
__device__ int    d_row_slot[TK];       // sorted row -> slot (t*2+k)
__device__ int    d_row_of_slot[TK];    // slot -> sorted row
__device__ __half d_act16[(size_t)TK * INT_DIM];  // weighted SwiGLU activations (fp16)
__device__ float  d_down[(size_t)TK * HID];

// ---------------- helpers ----------------
__device__ __forceinline__ uint32_t smem_u32(const void* p) {
    uint32_t a;
    asm("{ .reg .u64 t; cvta.to.shared.u64 t, %1; cvt.u32.u64 %0, t; }" : "=r"(a) : "l"(p));
    return a;
}
__device__ __forceinline__ void ldsm4(uint32_t& r0, uint32_t& r1, uint32_t& r2, uint32_t& r3,
                                      uint32_t addr) {
    asm volatile("ldmatrix.sync.aligned.m8n8.x4.shared.b16 {%0,%1,%2,%3}, [%4];"
                 : "=r"(r0), "=r"(r1), "=r"(r2), "=r"(r3) : "r"(addr));
}
__device__ __forceinline__ void mma16816(float& c0, float& c1, float& c2, float& c3,
                                         uint32_t a0, uint32_t a1, uint32_t a2, uint32_t a3,
                                         uint32_t b0, uint32_t b1) {
    asm volatile("mma.sync.aligned.m16n8k16.row.col.f32.f16.f16.f32 "
                 "{%0,%1,%2,%3}, {%4,%5,%6,%7}, {%8,%9}, {%0,%1,%2,%3};"
                 : "+f"(c0), "+f"(c1), "+f"(c2), "+f"(c3)
                 : "r"(a0), "r"(a1), "r"(a2), "r"(a3), "r"(b0), "r"(b1));
}
__device__ __forceinline__ void sts_f4_as_h4(__half* dst, float4 v) {
    __half2 h01 = __floats2half2_rn(v.x, v.y);
    __half2 h23 = __floats2half2_rn(v.z, v.w);
    uint2 u;
    u.x = *(uint32_t*)&h01;
    u.y = *(uint32_t*)&h23;
    *(uint2*)dst = u;
}

// ---------------- routing ----------------
__global__ void route_kernel(const int* __restrict__ topk) {
    __shared__ int s_cnt[NE];
    __shared__ int s_pos[NE];
    int tid = threadIdx.x;
    if (tid < NE) s_cnt[tid] = 0;
    __syncthreads();
    for (int s = tid; s < TK; s += blockDim.x)
        atomicAdd(&s_cnt[topk[s]], 1);
    __syncthreads();
    if (tid == 0) {
        int a = 0;
        for (int e = 0; e < NE; e++) { d_off[e] = a; s_pos[e] = a; a += s_cnt[e]; }
        d_off[NE] = a;
    }
    __syncthreads();
    for (int s = tid; s < TK; s += blockDim.x) {
        int e = topk[s];
        int r = atomicAdd(&s_pos[e], 1);
        d_row_slot[r]    = s;
        d_row_of_slot[s] = r;
    }
}

// ---------------- grouped GEMM via mma.sync (fp16 in, fp32 acc) ----------------
// PHASE 1: A = hidden (gathered, fp32->fp16), B rows = [gate nt..nt+63 | up nt..nt+63]
//          epilogue: SwiGLU * routing weight -> d_act16 (block covers 64 act cols)
// PHASE 2: A = d_act16 (contiguous), B = down_proj rows nt..nt+127 -> d_down fp32
template <int PHASE>
__global__ __launch_bounds__(256, 1) void moe_mma(
    const float* __restrict__ hidden, const float* __restrict__ Wsrc,
    const float* __restrict__ wts) {
    const int e   = blockIdx.z;
    const int off = d_off[e];
    const int cnt = d_off[e + 1] - off;
    const int rt  = blockIdx.y * 128;
    if (rt >= cnt) return;
    const int nt = blockIdx.x * (PHASE == 1 ? 64 : 128);  // act-col base / out-col base

    __shared__ __align__(16) char smem_raw[41984];
    __half* const Sh = (__half*)smem_raw;
    // As0 | Bs0 | As1 | Bs1, each 128 x LDS_H halves
    __half* As[2] = { Sh,                  Sh + 2 * TILE_HALVES };
    __half* Bs[2] = { Sh + TILE_HALVES,    Sh + 3 * TILE_HALVES };

    const int tid = threadIdx.x;
    const int wid = tid >> 5, lane = tid & 31;
    const int warp_m = wid & 1;       // 0..1 -> M offset *64
    const int warp_n = wid >> 1;      // 0..3 -> N offset *32

    const int K = HID;  // both phases K=2048
    const int NCH = K / BK;
    const float* W = Wsrc + (size_t)e * ((PHASE == 1) ? (size_t)N1 * HID : (size_t)HID * INT_DIM);

    // ---- load assignments ----
    // fp32 sources (A phase1, B both phases): 4 passes, row = i*32 + tid>>3, col = (tid&7)*4
    const int ldr  = tid >> 3;       // 0..31
    const int ldc  = (tid & 7) * 4;  // float col
    // A (phase1)
    const float* aptrF[4]; bool avalF[4]; int a_sts[4];
    // A (phase2, fp16 source): 2 passes, row = i*64 + tid>>2, col8 = (tid&3)*8 halves
    const __half* aptrH[2]; bool avalH[2]; int a_stsH[2];
    if (PHASE == 1) {
        #pragma unroll
        for (int i = 0; i < 4; i++) {
            int r  = i * 32 + ldr;
            int rg = rt + r;
            avalF[i] = rg < cnt;
            int tok  = avalF[i] ? (d_row_slot[off + rg] >> 1) : 0;
            aptrF[i] = hidden + (size_t)tok * HID + ldc;
            a_sts[i] = r * LDS_H + ldc;
        }
    } else {
        #pragma unroll
        for (int i = 0; i < 2; i++) {
            int r  = i * 64 + (tid >> 2);
            int rg = rt + r;
            avalH[i]  = rg < cnt;
            int col8  = (tid & 3) * 8;
            aptrH[i]  = d_act16 + (size_t)(off + (avalH[i] ? rg : 0)) * INT_DIM + col8;
            a_stsH[i] = r * LDS_H + col8;
        }
    }
    // B: 4 passes
    const float* bptr[4]; int b_sts[4];
    #pragma unroll
    for (int i = 0; i < 4; i++) {
        int r = i * 32 + ldr;
        int grow;
        if (PHASE == 1) grow = (r < 64) ? (nt + r) : (INT_DIM + nt + (r - 64));
        else            grow = nt + r;
        bptr[i]  = W + (size_t)grow * K + ldc;
        b_sts[i] = r * LDS_H + ldc;
    }

    // ldmatrix byte offsets within a tile (kk=0)
    int aOff[4], bOff[2];
    #pragma unroll
    for (int mi = 0; mi < 4; mi++)
        aOff[mi] = ((warp_m * 64 + mi * 16 + (lane & 15)) * LDS_H + (lane >> 4) * 8) * 2;
    #pragma unroll
    for (int g = 0; g < 2; g++)
        bOff[g] = ((warp_n * 32 + g * 16 + ((lane >> 4) & 1) * 8 + (lane & 7)) * LDS_H
                   + ((lane >> 3) & 1) * 8) * 2;

    float acc[4][4][4];
    #pragma unroll
    for (int mi = 0; mi < 4; mi++)
        #pragma unroll
        for (int ni = 0; ni < 4; ni++)
            #pragma unroll
            for (int q = 0; q < 4; q++) acc[mi][ni][q] = 0.f;

    // staging registers
    float4 aReg[4], bReg[4];
    uint4  aRegH[2];

    // ---- prologue: load + store tile 0 ----
    if (PHASE == 1) {
        #pragma unroll
        for (int i = 0; i < 4; i++)
            aReg[i] = avalF[i] ? *(const float4*)(aptrF[i]) : make_float4(0, 0, 0, 0);
    } else {
        #pragma unroll
        for (int i = 0; i < 2; i++)
            aRegH[i] = avalH[i] ? *(const uint4*)(aptrH[i]) : make_uint4(0, 0, 0, 0);
    }
    #pragma unroll
    for (int i = 0; i < 4; i++) bReg[i] = *(const float4*)(bptr[i]);

    if (PHASE == 1) {
        #pragma unroll
        for (int i = 0; i < 4; i++) sts_f4_as_h4(As[0] + a_sts[i], aReg[i]);
    } else {
        #pragma unroll
        for (int i = 0; i < 2; i++) *(uint4*)(As[0] + a_stsH[i]) = aRegH[i];
    }
    #pragma unroll
    for (int i = 0; i < 4; i++) sts_f4_as_h4(Bs[0] + b_sts[i], bReg[i]);
    __syncthreads();

    // ---- mainloop ----
    for (int c = 0; c < NCH; c++) {
        const int p = c & 1;
        if (c + 1 < NCH) {
            const int ko = (c + 1) * BK;
            if (PHASE == 1) {
                #pragma unroll
                for (int i = 0; i < 4; i++)
                    aReg[i] = avalF[i] ? *(const float4*)(aptrF[i] + ko) : make_float4(0, 0, 0, 0);
            } else {
                #pragma unroll
                for (int i = 0; i < 2; i++)
                    aRegH[i] = avalH[i] ? *(const uint4*)(aptrH[i] + ko) : make_uint4(0, 0, 0, 0);
            }
            #pragma unroll
            for (int i = 0; i < 4; i++) bReg[i] = *(const float4*)(bptr[i] + ko);
        }

        const uint32_t tA = smem_u32(As[p]);
        const uint32_t tB = smem_u32(Bs[p]);
        #pragma unroll
        for (int kk = 0; kk < 2; kk++) {
            const int kb = kk * 32;  // 16 halves = 32 bytes
            uint32_t a[4][4], b[4][2];
            #pragma unroll
            for (int mi = 0; mi < 4; mi++)
                ldsm4(a[mi][0], a[mi][1], a[mi][2], a[mi][3], tA + aOff[mi] + kb);
            #pragma unroll
            for (int g = 0; g < 2; g++)
                ldsm4(b[2 * g][0], b[2 * g][1], b[2 * g + 1][0], b[2 * g + 1][1],
                      tB + bOff[g] + kb);
            #pragma unroll
            for (int mi = 0; mi < 4; mi++)
                #pragma unroll
                for (int ni = 0; ni < 4; ni++)
                    mma16816(acc[mi][ni][0], acc[mi][ni][1], acc[mi][ni][2], acc[mi][ni][3],
                             a[mi][0], a[mi][1], a[mi][2], a[mi][3],
                             b[ni][0], b[ni][1]);
        }

        if (c + 1 < NCH) {
            const int pn = (c + 1) & 1;
            if (PHASE == 1) {
                #pragma unroll
                for (int i = 0; i < 4; i++) sts_f4_as_h4(As[pn] + a_sts[i], aReg[i]);
            } else {
                #pragma unroll
                for (int i = 0; i < 2; i++) *(uint4*)(As[pn] + a_stsH[i]) = aRegH[i];
            }
            #pragma unroll
            for (int i = 0; i < 4; i++) sts_f4_as_h4(Bs[pn] + b_sts[i], bReg[i]);
            __syncthreads();
        }
    }
    __syncthreads();  // smem reuse for epilogue exchange

    // ---- epilogue ----
    if (PHASE == 1) {
        // exch[row][actcol]: silu(gate) from warps n0/n1; up-warps combine
        float* exch = (float*)smem_raw;  // 128 x 66 fp32 = 33792B
        const int EP = 66;
        if (warp_n < 2) {
            #pragma unroll
            for (int mi = 0; mi < 4; mi++) {
                int row0 = warp_m * 64 + mi * 16 + (lane >> 2);
                #pragma unroll
                for (int ni = 0; ni < 4; ni++) {
                    int col = warp_n * 32 + ni * 8 + 2 * (lane & 3);
                    float g0 = acc[mi][ni][0], g1 = acc[mi][ni][1];
                    float g2 = acc[mi][ni][2], g3 = acc[mi][ni][3];
                    exch[row0 * EP + col]           = g0 / (1.f + __expf(-g0));
                    exch[row0 * EP + col + 1]       = g1 / (1.f + __expf(-g1));
                    exch[(row0 + 8) * EP + col]     = g2 / (1.f + __expf(-g2));
                    exch[(row0 + 8) * EP + col + 1] = g3 / (1.f + __expf(-g3));
                }
            }
        }
        __syncthreads();
        if (warp_n >= 2) {
            #pragma unroll
            for (int mi = 0; mi < 4; mi++) {
                int row0 = warp_m * 64 + mi * 16 + (lane >> 2);
                int rg0 = rt + row0, rg1 = rg0 + 8;
                bool v0 = rg0 < cnt, v1 = rg1 < cnt;
                float w0 = v0 ? wts[d_row_slot[off + rg0]] : 0.f;
                float w1 = v1 ? wts[d_row_slot[off + rg1]] : 0.f;
                #pragma unroll
                for (int ni = 0; ni < 4; ni++) {
                    int col = (warp_n - 2) * 32 + ni * 8 + 2 * (lane & 3);
                    float s0 = exch[row0 * EP + col];
                    float s1 = exch[row0 * EP + col + 1];
                    float s2 = exch[(row0 + 8) * EP + col];
                    float s3 = exch[(row0 + 8) * EP + col + 1];
                    float a0 = s0 * acc[mi][ni][0] * w0;
                    float a1 = s1 * acc[mi][ni][1] * w0;
                    float a2 = s2 * acc[mi][ni][2] * w1;
                    float a3 = s3 * acc[mi][ni][3] * w1;
                    if (v0) {
                        __half2 h = __floats2half2_rn(a0, a1);
                        *(uint32_t*)&d_act16[(size_t)(off + rg0) * INT_DIM + nt + col] =
                            *(uint32_t*)&h;
                    }
                    if (v1) {
                        __half2 h = __floats2half2_rn(a2, a3);
                        *(uint32_t*)&d_act16[(size_t)(off + rg1) * INT_DIM + nt + col] =
                            *(uint32_t*)&h;
                    }
                }
            }
        }
    } else {
        #pragma unroll
        for (int mi = 0; mi < 4; mi++) {
            int row0 = warp_m * 64 + mi * 16 + (lane >> 2);
            int rg0 = rt + row0, rg1 = rg0 + 8;
            bool v0 = rg0 < cnt, v1 = rg1 < cnt;
            #pragma unroll
            for (int ni = 0; ni < 4; ni++) {
                int col = nt + warp_n * 32 + ni * 8 + 2 * (lane & 3);
                if (v0) {
                    float2 o = make_float2(acc[mi][ni][0], acc[mi][ni][1]);
                    *(float2*)&d_down[(size_t)(off + rg0) * HID + col] = o;
                }
                if (v1) {
                    float2 o = make_float2(acc[mi][ni][2], acc[mi][ni][3]);
                    *(float2*)&d_down[(size_t)(off + rg1) * HID + col] = o;
                }
            }
        }
    }
}

// ---------------- combine ----------------
__global__ void combine_kernel(float* __restrict__ out) {
    size_t idx  = (size_t)blockIdx.x * blockDim.x + threadIdx.x;
    size_t base = idx * 4;
    if (base >= (size_t)NTOK * HID) return;
    int t = (int)(base / HID);
    int h = (int)(base % HID);
    int r0 = d_row_of_slot[2 * t];
    int r1 = d_row_of_slot[2 * t + 1];
    float4 x0 = *(const float4*)(d_down + (size_t)r0 * HID + h);
    float4 x1 = *(const float4*)(d_down + (size_t)r1 * HID + h);
    float4 o;
    o.x = x0.x + x1.x;
    o.y = x0.y + x1.y;
    o.z = x0.z + x1.z;
    o.w = x0.w + x1.w;
    *(float4*)(out + base) = o;
}

// ---------------- launcher ----------------
extern "C" void kernel_launch(void* const* d_in, const int* in_sizes, int n_in,
                              void* d_out, int out_size) {
    const float* hidden = (const float*)d_in[0];
    const int*   topk   = (const int*)  d_in[1];
    const float* wts    = (const float*)d_in[2];
    const float* gup    = (const float*)d_in[3];
    const float* downW  = (const float*)d_in[4];
    float* out = (float*)d_out;

    route_kernel<<<1, 256>>>(topk);
    moe_mma<1><<<dim3(INT_DIM / 64, TK / 128, NE), 256>>>(hidden, gup, wts);
    moe_mma<2><<<dim3(HID / 128, TK / 128, NE), 256>>>(nullptr, downW, nullptr);
    {
        size_t elems = (size_t)NTOK * HID / 4;
        combine_kernel<<<(unsigned)((elems + 255) / 256), 256>>>(out);
    }
}

// round 7
// speedup vs baseline: 4.6440x; 1.2771x over previous
#include <cuda_runtime.h>
#include <cuda_fp16.h>
#include <cstdint>

#define NE 8
#define HID 2048
#define INT_DIM 2048
#define NTOK 4096
#define TK 8192
#define N1 4096

#define BK 32            // k-floats per stage
#define BLKM 256         // rows per CTA
#define LDS_H 40         // halves per smem row (32 data + 8 pad = 80B)
#define A_TILE_H (BLKM * LDS_H)      // 10240 halves
#define B_TILE_H (128 * LDS_H)       // 5120 halves
#define STAGE_H  (A_TILE_H + B_TILE_H)
#define SMEM_DYN 67584   // max(2*STAGE_H*2B = 61440, exch 256*66*4 = 67584)

// ---------------- scratch ----------------
__device__ int    d_off[NE + 1];
__device__ int    d_row_slot[TK];       // sorted row -> slot (t*2+k)
__device__ int    d_row_of_slot[TK];    // slot -> sorted row
__device__ __half d_act16[(size_t)TK * INT_DIM];  // weighted SwiGLU activations (fp16)
__device__ float  d_down[(size_t)TK * HID];

// ---------------- helpers ----------------
__device__ __forceinline__ uint32_t smem_u32(const void* p) {
    uint32_t a;
    asm("{ .reg .u64 t; cvta.to.shared.u64 t, %1; cvt.u32.u64 %0, t; }" : "=r"(a) : "l"(p));
    return a;
}
__device__ __forceinline__ void ldsm4(uint32_t& r0, uint32_t& r1, uint32_t& r2, uint32_t& r3,
                                      uint32_t addr) {
    asm volatile("ldmatrix.sync.aligned.m8n8.x4.shared.b16 {%0,%1,%2,%3}, [%4];"
                 : "=r"(r0), "=r"(r1), "=r"(r2), "=r"(r3) : "r"(addr));
}
__device__ __forceinline__ void mma16816(float& c0, float& c1, float& c2, float& c3,
                                         uint32_t a0, uint32_t a1, uint32_t a2, uint32_t a3,
                                         uint32_t b0, uint32_t b1) {
    asm volatile("mma.sync.aligned.m16n8k16.row.col.f32.f16.f16.f32 "
                 "{%0,%1,%2,%3}, {%4,%5,%6,%7}, {%8,%9}, {%0,%1,%2,%3};"
                 : "+f"(c0), "+f"(c1), "+f"(c2), "+f"(c3)
                 : "r"(a0), "r"(a1), "r"(a2), "r"(a3), "r"(b0), "r"(b1));
}
__device__ __forceinline__ void sts_f4_as_h4(__half* dst, float4 v) {
    __half2 h01 = __floats2half2_rn(v.x, v.y);
    __half2 h23 = __floats2half2_rn(v.z, v.w);
    uint2 u;
    u.x = *(uint32_t*)&h01;
    u.y = *(uint32_t*)&h23;
    *(uint2*)dst = u;
}

// ---------------- routing ----------------
__global__ void route_kernel(const int* __restrict__ topk) {
    __shared__ int s_cnt[NE];
    __shared__ int s_pos[NE];
    int tid = threadIdx.x;
    if (tid < NE) s_cnt[tid] = 0;
    __syncthreads();
    for (int s = tid; s < TK; s += blockDim.x)
        atomicAdd(&s_cnt[topk[s]], 1);
    __syncthreads();
    if (tid == 0) {
        int a = 0;
        for (int e = 0; e < NE; e++) { d_off[e] = a; s_pos[e] = a; a += s_cnt[e]; }
        d_off[NE] = a;
    }
    __syncthreads();
    for (int s = tid; s < TK; s += blockDim.x) {
        int e = topk[s];
        int r = atomicAdd(&s_pos[e], 1);
        d_row_slot[r]    = s;
        d_row_of_slot[s] = r;
    }
}

// ---------------- grouped GEMM via mma.sync, 512 threads, 256-row tiles ----------------
// PHASE 1: A = hidden (gathered, fp32->fp16); B rows = [gate nt..nt+63 | up nt..nt+63]
//          epilogue: SwiGLU * routing weight -> d_act16 (64 act cols per block)
// PHASE 2: A = d_act16; B = down rows nt..nt+127 -> d_down fp32 (128 out cols)
template <int PHASE>
__global__ __launch_bounds__(512, 1) void moe_mma(
    const float* __restrict__ hidden, const float* __restrict__ Wsrc,
    const float* __restrict__ wts) {
    const int e   = blockIdx.z;
    const int off = d_off[e];
    const int cnt = d_off[e + 1] - off;
    const int rt  = blockIdx.y * BLKM;
    if (rt >= cnt) return;
    const int nt = blockIdx.x * (PHASE == 1 ? 64 : 128);

    extern __shared__ __align__(16) char smem_raw[];
    __half* const Sh = (__half*)smem_raw;
    __half* As[2] = { Sh,             Sh + STAGE_H };
    __half* Bs[2] = { Sh + A_TILE_H,  Sh + STAGE_H + A_TILE_H };

    const int tid  = threadIdx.x;
    const int wid  = tid >> 5, lane = tid & 31;
    const int wm   = wid >> 2;        // 0..3 -> M offset *64
    const int wn   = wid & 3;         // 0..3 -> N offset *32

    const int K   = HID;
    const int NCH = K / BK;
    const float* W = Wsrc + (size_t)e * ((PHASE == 1) ? (size_t)N1 * HID : (size_t)HID * INT_DIM);

    const int ldr = tid >> 3;        // 0..63
    const int ldc = (tid & 7) * 4;   // float col

    // A assignments
    const float*  aptrF[4]; bool avalF[4]; int a_sts[4];
    const __half* aptrH[2]; bool avalH[2]; int a_stsH[2];
    if (PHASE == 1) {
        #pragma unroll
        for (int i = 0; i < 4; i++) {
            int r  = i * 64 + ldr;
            int rg = rt + r;
            avalF[i] = rg < cnt;
            int tok  = avalF[i] ? (d_row_slot[off + rg] >> 1) : 0;
            aptrF[i] = hidden + (size_t)tok * HID + ldc;
            a_sts[i] = r * LDS_H + ldc;
        }
    } else {
        #pragma unroll
        for (int i = 0; i < 2; i++) {
            int r  = i * 128 + (tid >> 2);
            int rg = rt + r;
            avalH[i]  = rg < cnt;
            int col8  = (tid & 3) * 8;
            aptrH[i]  = d_act16 + (size_t)(off + (avalH[i] ? rg : 0)) * INT_DIM + col8;
            a_stsH[i] = r * LDS_H + col8;
        }
    }
    // B assignments: 2 passes over 128 rows
    const float* bptr[2]; int b_sts[2];
    #pragma unroll
    for (int i = 0; i < 2; i++) {
        int r = i * 64 + ldr;
        int grow;
        if (PHASE == 1) grow = (r < 64) ? (nt + r) : (INT_DIM + nt + (r - 64));
        else            grow = nt + r;
        bptr[i]  = W + (size_t)grow * K + ldc;
        b_sts[i] = r * LDS_H + ldc;
    }

    // ldmatrix byte offsets (kk=0)
    int aOff[4], bOff[2];
    #pragma unroll
    for (int mi = 0; mi < 4; mi++)
        aOff[mi] = ((wm * 64 + mi * 16 + (lane & 15)) * LDS_H + (lane >> 4) * 8) * 2;
    #pragma unroll
    for (int g = 0; g < 2; g++)
        bOff[g] = ((wn * 32 + g * 16 + ((lane >> 4) & 1) * 8 + (lane & 7)) * LDS_H
                   + ((lane >> 3) & 1) * 8) * 2;

    float acc[4][4][4];
    #pragma unroll
    for (int mi = 0; mi < 4; mi++)
        #pragma unroll
        for (int ni = 0; ni < 4; ni++)
            #pragma unroll
            for (int q = 0; q < 4; q++) acc[mi][ni][q] = 0.f;

    float4 aReg[4], bReg[2];
    uint4  aRegH[2];

    // prologue
    if (PHASE == 1) {
        #pragma unroll
        for (int i = 0; i < 4; i++)
            aReg[i] = avalF[i] ? *(const float4*)(aptrF[i]) : make_float4(0, 0, 0, 0);
    } else {
        #pragma unroll
        for (int i = 0; i < 2; i++)
            aRegH[i] = avalH[i] ? *(const uint4*)(aptrH[i]) : make_uint4(0, 0, 0, 0);
    }
    #pragma unroll
    for (int i = 0; i < 2; i++) bReg[i] = *(const float4*)(bptr[i]);

    if (PHASE == 1) {
        #pragma unroll
        for (int i = 0; i < 4; i++) sts_f4_as_h4(As[0] + a_sts[i], aReg[i]);
    } else {
        #pragma unroll
        for (int i = 0; i < 2; i++) *(uint4*)(As[0] + a_stsH[i]) = aRegH[i];
    }
    #pragma unroll
    for (int i = 0; i < 2; i++) sts_f4_as_h4(Bs[0] + b_sts[i], bReg[i]);
    __syncthreads();

    // mainloop
    for (int c = 0; c < NCH; c++) {
        const int p = c & 1;
        if (c + 1 < NCH) {
            const int ko = (c + 1) * BK;
            if (PHASE == 1) {
                #pragma unroll
                for (int i = 0; i < 4; i++)
                    aReg[i] = avalF[i] ? *(const float4*)(aptrF[i] + ko) : make_float4(0, 0, 0, 0);
            } else {
                #pragma unroll
                for (int i = 0; i < 2; i++)
                    aRegH[i] = avalH[i] ? *(const uint4*)(aptrH[i] + ko) : make_uint4(0, 0, 0, 0);
            }
            #pragma unroll
            for (int i = 0; i < 2; i++) bReg[i] = *(const float4*)(bptr[i] + ko);
        }

        const uint32_t tA = smem_u32(As[p]);
        const uint32_t tB = smem_u32(Bs[p]);
        #pragma unroll
        for (int kk = 0; kk < 2; kk++) {
            const int kb = kk * 32;
            uint32_t a[4][4], b[4][2];
            #pragma unroll
            for (int mi = 0; mi < 4; mi++)
                ldsm4(a[mi][0], a[mi][1], a[mi][2], a[mi][3], tA + aOff[mi] + kb);
            #pragma unroll
            for (int g = 0; g < 2; g++)
                ldsm4(b[2 * g][0], b[2 * g][1], b[2 * g + 1][0], b[2 * g + 1][1],
                      tB + bOff[g] + kb);
            #pragma unroll
            for (int mi = 0; mi < 4; mi++)
                #pragma unroll
                for (int ni = 0; ni < 4; ni++)
                    mma16816(acc[mi][ni][0], acc[mi][ni][1], acc[mi][ni][2], acc[mi][ni][3],
                             a[mi][0], a[mi][1], a[mi][2], a[mi][3],
                             b[ni][0], b[ni][1]);
        }

        if (c + 1 < NCH) {
            const int pn = (c + 1) & 1;
            if (PHASE == 1) {
                #pragma unroll
                for (int i = 0; i < 4; i++) sts_f4_as_h4(As[pn] + a_sts[i], aReg[i]);
            } else {
                #pragma unroll
                for (int i = 0; i < 2; i++) *(uint4*)(As[pn] + a_stsH[i]) = aRegH[i];
            }
            #pragma unroll
            for (int i = 0; i < 2; i++) sts_f4_as_h4(Bs[pn] + b_sts[i], bReg[i]);
            __syncthreads();
        }
    }
    __syncthreads();  // smem reuse for epilogue

    if (PHASE == 1) {
        float* exch = (float*)smem_raw;  // 256 x 66 fp32
        const int EP = 66;
        if (wn < 2) {
            #pragma unroll
            for (int mi = 0; mi < 4; mi++) {
                int row0 = wm * 64 + mi * 16 + (lane >> 2);
                #pragma unroll
                for (int ni = 0; ni < 4; ni++) {
                    int col = wn * 32 + ni * 8 + 2 * (lane & 3);
                    float g0 = acc[mi][ni][0], g1 = acc[mi][ni][1];
                    float g2 = acc[mi][ni][2], g3 = acc[mi][ni][3];
                    exch[row0 * EP + col]           = g0 / (1.f + __expf(-g0));
                    exch[row0 * EP + col + 1]       = g1 / (1.f + __expf(-g1));
                    exch[(row0 + 8) * EP + col]     = g2 / (1.f + __expf(-g2));
                    exch[(row0 + 8) * EP + col + 1] = g3 / (1.f + __expf(-g3));
                }
            }
        }
        __syncthreads();
        if (wn >= 2) {
            #pragma unroll
            for (int mi = 0; mi < 4; mi++) {
                int row0 = wm * 64 + mi * 16 + (lane >> 2);
                int rg0 = rt + row0, rg1 = rg0 + 8;
                bool v0 = rg0 < cnt, v1 = rg1 < cnt;
                float w0 = v0 ? wts[d_row_slot[off + rg0]] : 0.f;
                float w1 = v1 ? wts[d_row_slot[off + rg1]] : 0.f;
                #pragma unroll
                for (int ni = 0; ni < 4; ni++) {
                    int col = (wn - 2) * 32 + ni * 8 + 2 * (lane & 3);
                    float s0 = exch[row0 * EP + col];
                    float s1 = exch[row0 * EP + col + 1];
                    float s2 = exch[(row0 + 8) * EP + col];
                    float s3 = exch[(row0 + 8) * EP + col + 1];
                    float a0 = s0 * acc[mi][ni][0] * w0;
                    float a1 = s1 * acc[mi][ni][1] * w0;
                    float a2 = s2 * acc[mi][ni][2] * w1;
                    float a3 = s3 * acc[mi][ni][3] * w1;
                    if (v0) {
                        __half2 h = __floats2half2_rn(a0, a1);
                        *(uint32_t*)&d_act16[(size_t)(off + rg0) * INT_DIM + nt + col] =
                            *(uint32_t*)&h;
                    }
                    if (v1) {
                        __half2 h = __floats2half2_rn(a2, a3);
                        *(uint32_t*)&d_act16[(size_t)(off + rg1) * INT_DIM + nt + col] =
                            *(uint32_t*)&h;
                    }
                }
            }
        }
    } else {
        #pragma unroll
        for (int mi = 0; mi < 4; mi++) {
            int row0 = wm * 64 + mi * 16 + (lane >> 2);
            int rg0 = rt + row0, rg1 = rg0 + 8;
            bool v0 = rg0 < cnt, v1 = rg1 < cnt;
            #pragma unroll
            for (int ni = 0; ni < 4; ni++) {
                int col = nt + wn * 32 + ni * 8 + 2 * (lane & 3);
                if (v0) {
                    float2 o = make_float2(acc[mi][ni][0], acc[mi][ni][1]);
                    *(float2*)&d_down[(size_t)(off + rg0) * HID + col] = o;
                }
                if (v1) {
                    float2 o = make_float2(acc[mi][ni][2], acc[mi][ni][3]);
                    *(float2*)&d_down[(size_t)(off + rg1) * HID + col] = o;
                }
            }
        }
    }
}

// ---------------- combine ----------------
__global__ void combine_kernel(float* __restrict__ out) {
    size_t idx  = (size_t)blockIdx.x * blockDim.x + threadIdx.x;
    size_t base = idx * 4;
    if (base >= (size_t)NTOK * HID) return;
    int t = (int)(base / HID);
    int h = (int)(base % HID);
    int r0 = d_row_of_slot[2 * t];
    int r1 = d_row_of_slot[2 * t + 1];
    float4 x0 = *(const float4*)(d_down + (size_t)r0 * HID + h);
    float4 x1 = *(const float4*)(d_down + (size_t)r1 * HID + h);
    float4 o;
    o.x = x0.x + x1.x;
    o.y = x0.y + x1.y;
    o.z = x0.z + x1.z;
    o.w = x0.w + x1.w;
    *(float4*)(out + base) = o;
}

// ---------------- launcher ----------------
extern "C" void kernel_launch(void* const* d_in, const int* in_sizes, int n_in,
                              void* d_out, int out_size) {
    const float* hidden = (const float*)d_in[0];
    const int*   topk   = (const int*)  d_in[1];
    const float* wts    = (const float*)d_in[2];
    const float* gup    = (const float*)d_in[3];
    const float* downW  = (const float*)d_in[4];
    float* out = (float*)d_out;

    cudaFuncSetAttribute(moe_mma<1>, cudaFuncAttributeMaxDynamicSharedMemorySize, SMEM_DYN);
    cudaFuncSetAttribute(moe_mma<2>, cudaFuncAttributeMaxDynamicSharedMemorySize, SMEM_DYN);

    route_kernel<<<1, 256>>>(topk);
    moe_mma<1><<<dim3(INT_DIM / 64, TK / BLKM, NE), 512, SMEM_DYN>>>(hidden, gup, wts);
    moe_mma<2><<<dim3(HID / 128, TK / BLKM, NE), 512, SMEM_DYN>>>(nullptr, downW, nullptr);
    {
        size_t elems = (size_t)NTOK * HID / 4;
        combine_kernel<<<(unsigned)((elems + 255) / 256), 256>>>(out);
    }
}

// round 8
// speedup vs baseline: 5.6765x; 1.2223x over previous
#include <cuda_runtime.h>
#include <cuda_fp16.h>
#include <cstdint>

#define NE 8
#define HID 2048
#define INT_DIM 2048
#define NTOK 4096
#define TK 8192
#define N1 4096

#define BKH 64            // k-halves per stage (128B rows)
#define BLKM 256          // rows per CTA
#define LDS_H 72          // halves per smem row (64 data + 8 pad = 144B)
#define A_TILE_BYTES (BLKM * LDS_H * 2)     // 36864
#define B_OFF        A_TILE_BYTES
#define B_TILE_BYTES (128 * LDS_H * 2)      // 18432
#define STAGE_BYTES  (A_TILE_BYTES + B_TILE_BYTES)  // 55296
#define NSTAGE 3
#define SMEM_DYN (NSTAGE * STAGE_BYTES)     // 165888

// ---------------- scratch ----------------
__device__ int    d_off[NE + 1];
__device__ int    d_row_slot[TK];
__device__ int    d_row_of_slot[TK];
__device__ __half d_hid16[(size_t)NTOK * HID];
__device__ __half d_w1h[(size_t)NE * N1 * HID];
__device__ __half d_w2h[(size_t)NE * HID * INT_DIM];
__device__ __half d_act16[(size_t)TK * INT_DIM];
__device__ float  d_down[(size_t)TK * HID];

// ---------------- helpers ----------------
__device__ __forceinline__ uint32_t smem_u32(const void* p) {
    uint32_t a;
    asm("{ .reg .u64 t; cvta.to.shared.u64 t, %1; cvt.u32.u64 %0, t; }" : "=r"(a) : "l"(p));
    return a;
}
__device__ __forceinline__ void ldsm4(uint32_t& r0, uint32_t& r1, uint32_t& r2, uint32_t& r3,
                                      uint32_t addr) {
    asm volatile("ldmatrix.sync.aligned.m8n8.x4.shared.b16 {%0,%1,%2,%3}, [%4];"
                 : "=r"(r0), "=r"(r1), "=r"(r2), "=r"(r3) : "r"(addr));
}
__device__ __forceinline__ void mma16816(float& c0, float& c1, float& c2, float& c3,
                                         uint32_t a0, uint32_t a1, uint32_t a2, uint32_t a3,
                                         uint32_t b0, uint32_t b1) {
    asm volatile("mma.sync.aligned.m16n8k16.row.col.f32.f16.f16.f32 "
                 "{%0,%1,%2,%3}, {%4,%5,%6,%7}, {%8,%9}, {%0,%1,%2,%3};"
                 : "+f"(c0), "+f"(c1), "+f"(c2), "+f"(c3)
                 : "r"(a0), "r"(a1), "r"(a2), "r"(a3), "r"(b0), "r"(b1));
}
__device__ __forceinline__ void cp16(uint32_t dst, const void* src, bool pred) {
    int sz = pred ? 16 : 0;
    asm volatile("cp.async.cg.shared.global [%0], [%1], 16, %2;"
                 :: "r"(dst), "l"(src), "r"(sz) : "memory");
}
#define CP_COMMIT() asm volatile("cp.async.commit_group;" ::: "memory")
#define CP_WAIT(n)  asm volatile("cp.async.wait_group %0;" :: "n"(n) : "memory")

// ---------------- fp32 -> fp16 conversion (grid-stride, float4 -> half4) ----------------
__global__ void cvt_kernel(const float* __restrict__ src, __half* __restrict__ dst, int n4) {
    int i = blockIdx.x * blockDim.x + threadIdx.x;
    int stride = gridDim.x * blockDim.x;
    for (; i < n4; i += stride) {
        float4 v = *(const float4*)(src + (size_t)i * 4);
        __half2 h01 = __floats2half2_rn(v.x, v.y);
        __half2 h23 = __floats2half2_rn(v.z, v.w);
        uint2 u;
        u.x = *(uint32_t*)&h01;
        u.y = *(uint32_t*)&h23;
        *(uint2*)(dst + (size_t)i * 4) = u;
    }
}

// ---------------- routing ----------------
__global__ void route_kernel(const int* __restrict__ topk) {
    __shared__ int s_cnt[NE];
    __shared__ int s_pos[NE];
    int tid = threadIdx.x;
    if (tid < NE) s_cnt[tid] = 0;
    __syncthreads();
    for (int s = tid; s < TK; s += blockDim.x)
        atomicAdd(&s_cnt[topk[s]], 1);
    __syncthreads();
    if (tid == 0) {
        int a = 0;
        for (int e = 0; e < NE; e++) { d_off[e] = a; s_pos[e] = a; a += s_cnt[e]; }
        d_off[NE] = a;
    }
    __syncthreads();
    for (int s = tid; s < TK; s += blockDim.x) {
        int e = topk[s];
        int r = atomicAdd(&s_pos[e], 1);
        d_row_slot[r]    = s;
        d_row_of_slot[s] = r;
    }
}

// ---------------- grouped GEMM: cp.async 3-stage, all-fp16 operands ----------------
// PHASE 1: A = d_hid16 (gathered); B rows = [gate nt..nt+63 | up nt..nt+63] of d_w1h
//          epilogue: SwiGLU * routing weight -> d_act16 (64 act cols per block)
// PHASE 2: A = d_act16; B = d_w2h rows nt..nt+127 -> d_down fp32
template <int PHASE>
__global__ __launch_bounds__(512, 1) void moe_mma(const float* __restrict__ wts) {
    const int e   = blockIdx.z;
    const int off = d_off[e];
    const int cnt = d_off[e + 1] - off;
    const int rt  = blockIdx.y * BLKM;
    if (rt >= cnt) return;
    const int nt = blockIdx.x * (PHASE == 1 ? 64 : 128);

    extern __shared__ __align__(16) char smem_raw[];
    const uint32_t sb = smem_u32(smem_raw);

    const int tid  = threadIdx.x;
    const int wid  = tid >> 5, lane = tid & 31;
    const int wm   = wid >> 2;
    const int wn   = wid & 3;

    const int K = HID;  // halves per row, both phases
    const int NCH = K / BKH;  // 32
    const __half* Wh = (PHASE == 1)
        ? d_w1h + (size_t)e * N1 * HID
        : d_w2h + (size_t)e * HID * INT_DIM;

    // ---- cp.async assignments ----
    // A: 4 chunks/thread over 256 rows x 8 x16B; B: 2 chunks/thread over 128 rows x 8
    const __half* aSrc[4]; bool aval[4]; uint32_t aDst[4];
    #pragma unroll
    for (int i = 0; i < 4; i++) {
        int chunk = i * 512 + tid;
        int row = chunk >> 3, c16 = chunk & 7;
        int rg = rt + row;
        aval[i] = rg < cnt;
        aDst[i] = (uint32_t)(row * (LDS_H * 2) + c16 * 16);
        if (PHASE == 1) {
            int tok = aval[i] ? (d_row_slot[off + rg] >> 1) : 0;
            aSrc[i] = d_hid16 + (size_t)tok * HID + c16 * 8;
        } else {
            aSrc[i] = d_act16 + (size_t)(off + (aval[i] ? rg : 0)) * INT_DIM + c16 * 8;
        }
    }
    const __half* bSrc[2]; uint32_t bDst[2];
    #pragma unroll
    for (int i = 0; i < 2; i++) {
        int chunk = i * 512 + tid;
        int row = chunk >> 3, c16 = chunk & 7;
        int grow;
        if (PHASE == 1) grow = (row < 64) ? (nt + row) : (INT_DIM + nt + (row - 64));
        else            grow = nt + row;
        bDst[i] = (uint32_t)(B_OFF + row * (LDS_H * 2) + c16 * 16);
        bSrc[i] = Wh + (size_t)grow * K + c16 * 8;
    }

    // ldmatrix byte offsets (kk = 0)
    int aOff[4], bOff[2];
    #pragma unroll
    for (int mi = 0; mi < 4; mi++)
        aOff[mi] = ((wm * 64 + mi * 16 + (lane & 15)) * LDS_H) * 2 + (lane >> 4) * 16;
    #pragma unroll
    for (int g = 0; g < 2; g++)
        bOff[g] = B_OFF + ((wn * 32 + g * 16 + ((lane >> 4) & 1) * 8 + (lane & 7)) * LDS_H) * 2
                  + ((lane >> 3) & 1) * 16;

    float acc[4][4][4];
    #pragma unroll
    for (int mi = 0; mi < 4; mi++)
        #pragma unroll
        for (int ni = 0; ni < 4; ni++)
            #pragma unroll
            for (int q = 0; q < 4; q++) acc[mi][ni][q] = 0.f;

    // ---- pipeline ----
    #define ISSUE(ks) do {                                              \
        uint32_t _base = sb + ((ks) % NSTAGE) * STAGE_BYTES;            \
        int _ko = (ks) * BKH;                                           \
        _Pragma("unroll")                                               \
        for (int _i = 0; _i < 4; _i++)                                  \
            cp16(_base + aDst[_i], aSrc[_i] + _ko, aval[_i]);           \
        _Pragma("unroll")                                               \
        for (int _i = 0; _i < 2; _i++)                                  \
            cp16(_base + bDst[_i], bSrc[_i] + _ko, true);               \
        CP_COMMIT();                                                    \
    } while (0)

    ISSUE(0);
    ISSUE(1);

    for (int c = 0; c < NCH; c++) {
        if (c + 2 < NCH) CP_WAIT(1); else CP_WAIT(0);
        __syncthreads();
        if (c + 2 < NCH) ISSUE(c + 2);

        const uint32_t st = sb + (c % NSTAGE) * STAGE_BYTES;
        #pragma unroll
        for (int kk = 0; kk < 4; kk++) {
            const int kb = kk * 32;
            uint32_t a[4][4], b[4][2];
            #pragma unroll
            for (int mi = 0; mi < 4; mi++)
                ldsm4(a[mi][0], a[mi][1], a[mi][2], a[mi][3], st + aOff[mi] + kb);
            #pragma unroll
            for (int g = 0; g < 2; g++)
                ldsm4(b[2 * g][0], b[2 * g][1], b[2 * g + 1][0], b[2 * g + 1][1],
                      st + bOff[g] + kb);
            #pragma unroll
            for (int mi = 0; mi < 4; mi++)
                #pragma unroll
                for (int ni = 0; ni < 4; ni++)
                    mma16816(acc[mi][ni][0], acc[mi][ni][1], acc[mi][ni][2], acc[mi][ni][3],
                             a[mi][0], a[mi][1], a[mi][2], a[mi][3],
                             b[ni][0], b[ni][1]);
        }
        __syncthreads();
    }
    #undef ISSUE

    // ---- epilogue ----
    if (PHASE == 1) {
        float* exch = (float*)smem_raw;  // 256 x 66 fp32 = 67584 <= SMEM_DYN
        const int EP = 66;
        if (wn < 2) {
            #pragma unroll
            for (int mi = 0; mi < 4; mi++) {
                int row0 = wm * 64 + mi * 16 + (lane >> 2);
                #pragma unroll
                for (int ni = 0; ni < 4; ni++) {
                    int col = wn * 32 + ni * 8 + 2 * (lane & 3);
                    float g0 = acc[mi][ni][0], g1 = acc[mi][ni][1];
                    float g2 = acc[mi][ni][2], g3 = acc[mi][ni][3];
                    exch[row0 * EP + col]           = g0 / (1.f + __expf(-g0));
                    exch[row0 * EP + col + 1]       = g1 / (1.f + __expf(-g1));
                    exch[(row0 + 8) * EP + col]     = g2 / (1.f + __expf(-g2));
                    exch[(row0 + 8) * EP + col + 1] = g3 / (1.f + __expf(-g3));
                }
            }
        }
        __syncthreads();
        if (wn >= 2) {
            #pragma unroll
            for (int mi = 0; mi < 4; mi++) {
                int row0 = wm * 64 + mi * 16 + (lane >> 2);
                int rg0 = rt + row0, rg1 = rg0 + 8;
                bool v0 = rg0 < cnt, v1 = rg1 < cnt;
                float w0 = v0 ? wts[d_row_slot[off + rg0]] : 0.f;
                float w1 = v1 ? wts[d_row_slot[off + rg1]] : 0.f;
                #pragma unroll
                for (int ni = 0; ni < 4; ni++) {
                    int col = (wn - 2) * 32 + ni * 8 + 2 * (lane & 3);
                    float s0 = exch[row0 * EP + col];
                    float s1 = exch[row0 * EP + col + 1];
                    float s2 = exch[(row0 + 8) * EP + col];
                    float s3 = exch[(row0 + 8) * EP + col + 1];
                    float a0 = s0 * acc[mi][ni][0] * w0;
                    float a1 = s1 * acc[mi][ni][1] * w0;
                    float a2 = s2 * acc[mi][ni][2] * w1;
                    float a3 = s3 * acc[mi][ni][3] * w1;
                    if (v0) {
                        __half2 h = __floats2half2_rn(a0, a1);
                        *(uint32_t*)&d_act16[(size_t)(off + rg0) * INT_DIM + nt + col] =
                            *(uint32_t*)&h;
                    }
                    if (v1) {
                        __half2 h = __floats2half2_rn(a2, a3);
                        *(uint32_t*)&d_act16[(size_t)(off + rg1) * INT_DIM + nt + col] =
                            *(uint32_t*)&h;
                    }
                }
            }
        }
    } else {
        #pragma unroll
        for (int mi = 0; mi < 4; mi++) {
            int row0 = wm * 64 + mi * 16 + (lane >> 2);
            int rg0 = rt + row0, rg1 = rg0 + 8;
            bool v0 = rg0 < cnt, v1 = rg1 < cnt;
            #pragma unroll
            for (int ni = 0; ni < 4; ni++) {
                int col = nt + wn * 32 + ni * 8 + 2 * (lane & 3);
                if (v0) {
                    float2 o = make_float2(acc[mi][ni][0], acc[mi][ni][1]);
                    *(float2*)&d_down[(size_t)(off + rg0) * HID + col] = o;
                }
                if (v1) {
                    float2 o = make_float2(acc[mi][ni][2], acc[mi][ni][3]);
                    *(float2*)&d_down[(size_t)(off + rg1) * HID + col] = o;
                }
            }
        }
    }
}

// ---------------- combine ----------------
__global__ void combine_kernel(float* __restrict__ out) {
    size_t idx  = (size_t)blockIdx.x * blockDim.x + threadIdx.x;
    size_t base = idx * 4;
    if (base >= (size_t)NTOK * HID) return;
    int t = (int)(base / HID);
    int h = (int)(base % HID);
    int r0 = d_row_of_slot[2 * t];
    int r1 = d_row_of_slot[2 * t + 1];
    float4 x0 = *(const float4*)(d_down + (size_t)r0 * HID + h);
    float4 x1 = *(const float4*)(d_down + (size_t)r1 * HID + h);
    float4 o;
    o.x = x0.x + x1.x;
    o.y = x0.y + x1.y;
    o.z = x0.z + x1.z;
    o.w = x0.w + x1.w;
    *(float4*)(out + base) = o;
}

// ---------------- launcher ----------------
extern "C" void kernel_launch(void* const* d_in, const int* in_sizes, int n_in,
                              void* d_out, int out_size) {
    const float* hidden = (const float*)d_in[0];
    const int*   topk   = (const int*)  d_in[1];
    const float* wts    = (const float*)d_in[2];
    const float* gup    = (const float*)d_in[3];
    const float* downW  = (const float*)d_in[4];
    float* out = (float*)d_out;

    cudaFuncSetAttribute(moe_mma<1>, cudaFuncAttributeMaxDynamicSharedMemorySize, SMEM_DYN);
    cudaFuncSetAttribute(moe_mma<2>, cudaFuncAttributeMaxDynamicSharedMemorySize, SMEM_DYN);

    __half* hid16p; cudaGetSymbolAddress((void**)&hid16p, d_hid16);
    __half* w1p;    cudaGetSymbolAddress((void**)&w1p,    d_w1h);
    __half* w2p;    cudaGetSymbolAddress((void**)&w2p,    d_w2h);

    route_kernel<<<1, 256>>>(topk);
    {
        int n4h = NTOK * HID / 4;
        cvt_kernel<<<1184, 256>>>(hidden, hid16p, n4h);
        int n41 = NE * N1 * HID / 4;
        cvt_kernel<<<4736, 256>>>(gup, w1p, n41);
        int n42 = NE * HID * INT_DIM / 4;
        cvt_kernel<<<4736, 256>>>(downW, w2p, n42);
    }
    moe_mma<1><<<dim3(INT_DIM / 64, TK / BLKM, NE), 512, SMEM_DYN>>>(wts);
    moe_mma<2><<<dim3(HID / 128, TK / BLKM, NE), 512, SMEM_DYN>>>(wts);
    {
        size_t elems = (size_t)NTOK * HID / 4;
        combine_kernel<<<(unsigned)((elems + 255) / 256), 256>>>(out);
    }
}

// round 9
// speedup vs baseline: 5.7332x; 1.0100x over previous
#include <cuda_runtime.h>
#include <cuda_fp16.h>
#include <cstdint>

#define NE 8
#define HID 2048
#define INT_DIM 2048
#define NTOK 4096
#define TK 8192
#define N1 4096

#define BKH 64            // k-halves per stage (128B rows)
#define BLKM 256          // rows per CTA
#define LDS_H 72          // halves per smem row (64 data + 8 pad = 144B)
#define A_TILE_BYTES (BLKM * LDS_H * 2)     // 36864
#define B_OFF        A_TILE_BYTES
#define B_TILE_BYTES (128 * LDS_H * 2)      // 18432
#define STAGE_BYTES  (A_TILE_BYTES + B_TILE_BYTES)  // 55296
#define NSTAGE 4
#define SMEM_DYN (NSTAGE * STAGE_BYTES)     // 221184

// ---------------- scratch ----------------
__device__ int    d_off[NE + 1];
__device__ int    d_row_slot[TK];
__device__ int    d_row_of_slot[TK];
__device__ __half d_hid16[(size_t)NTOK * HID];
__device__ __half d_w1h[(size_t)NE * N1 * HID];
__device__ __half d_w2h[(size_t)NE * HID * INT_DIM];
__device__ __half d_act16[(size_t)TK * INT_DIM];

// ---------------- helpers ----------------
__device__ __forceinline__ uint32_t smem_u32(const void* p) {
    uint32_t a;
    asm("{ .reg .u64 t; cvta.to.shared.u64 t, %1; cvt.u32.u64 %0, t; }" : "=r"(a) : "l"(p));
    return a;
}
__device__ __forceinline__ void ldsm4(uint32_t& r0, uint32_t& r1, uint32_t& r2, uint32_t& r3,
                                      uint32_t addr) {
    asm volatile("ldmatrix.sync.aligned.m8n8.x4.shared.b16 {%0,%1,%2,%3}, [%4];"
                 : "=r"(r0), "=r"(r1), "=r"(r2), "=r"(r3) : "r"(addr));
}
__device__ __forceinline__ void mma16816(float& c0, float& c1, float& c2, float& c3,
                                         uint32_t a0, uint32_t a1, uint32_t a2, uint32_t a3,
                                         uint32_t b0, uint32_t b1) {
    asm volatile("mma.sync.aligned.m16n8k16.row.col.f32.f16.f16.f32 "
                 "{%0,%1,%2,%3}, {%4,%5,%6,%7}, {%8,%9}, {%0,%1,%2,%3};"
                 : "+f"(c0), "+f"(c1), "+f"(c2), "+f"(c3)
                 : "r"(a0), "r"(a1), "r"(a2), "r"(a3), "r"(b0), "r"(b1));
}
__device__ __forceinline__ void cp16(uint32_t dst, const void* src, bool pred) {
    int sz = pred ? 16 : 0;
    asm volatile("cp.async.cg.shared.global [%0], [%1], 16, %2;"
                 :: "r"(dst), "l"(src), "r"(sz) : "memory");
}
#define CP_COMMIT() asm volatile("cp.async.commit_group;" ::: "memory")
#define CP_WAIT(n)  asm volatile("cp.async.wait_group %0;" :: "n"(n) : "memory")

// ---------------- fp32 -> fp16 conversion (streaming reads) ----------------
__global__ void cvt_kernel(const float* __restrict__ src, __half* __restrict__ dst, int n4) {
    int i = blockIdx.x * blockDim.x + threadIdx.x;
    int stride = gridDim.x * blockDim.x;
    for (; i < n4; i += stride) {
        float4 v = __ldcs((const float4*)(src + (size_t)i * 4));
        __half2 h01 = __floats2half2_rn(v.x, v.y);
        __half2 h23 = __floats2half2_rn(v.z, v.w);
        uint2 u;
        u.x = *(uint32_t*)&h01;
        u.y = *(uint32_t*)&h23;
        *(uint2*)(dst + (size_t)i * 4) = u;
    }
}

// ---------------- zero output ----------------
__global__ void zero_kernel(float* __restrict__ out, int n4) {
    int i = blockIdx.x * blockDim.x + threadIdx.x;
    int stride = gridDim.x * blockDim.x;
    for (; i < n4; i += stride)
        *(float4*)(out + (size_t)i * 4) = make_float4(0.f, 0.f, 0.f, 0.f);
}

// ---------------- routing ----------------
__global__ void route_kernel(const int* __restrict__ topk) {
    __shared__ int s_cnt[NE];
    __shared__ int s_pos[NE];
    int tid = threadIdx.x;
    if (tid < NE) s_cnt[tid] = 0;
    __syncthreads();
    for (int s = tid; s < TK; s += blockDim.x)
        atomicAdd(&s_cnt[topk[s]], 1);
    __syncthreads();
    if (tid == 0) {
        int a = 0;
        for (int e = 0; e < NE; e++) { d_off[e] = a; s_pos[e] = a; a += s_cnt[e]; }
        d_off[NE] = a;
    }
    __syncthreads();
    for (int s = tid; s < TK; s += blockDim.x) {
        int e = topk[s];
        int r = atomicAdd(&s_pos[e], 1);
        d_row_slot[r]    = s;
        d_row_of_slot[s] = r;
    }
}

// ---------------- grouped GEMM: cp.async 4-stage, all-fp16 operands ----------------
// PHASE 1: A = d_hid16 (gathered); B rows = [gate nt..nt+63 | up nt..nt+63] of d_w1h
//          epilogue: SwiGLU * routing weight -> d_act16 (64 act cols per block)
// PHASE 2: A = d_act16; B = d_w2h rows nt..nt+127; epilogue: atomicAdd into out
template <int PHASE>
__global__ __launch_bounds__(512, 1) void moe_mma(const float* __restrict__ wts,
                                                  float* __restrict__ out) {
    const int e   = blockIdx.z;
    const int off = d_off[e];
    const int cnt = d_off[e + 1] - off;
    const int rt  = blockIdx.y * BLKM;
    if (rt >= cnt) return;
    const int nt = blockIdx.x * (PHASE == 1 ? 64 : 128);

    extern __shared__ __align__(16) char smem_raw[];
    const uint32_t sb = smem_u32(smem_raw);

    const int tid  = threadIdx.x;
    const int wid  = tid >> 5, lane = tid & 31;
    const int wm   = wid >> 2;
    const int wn   = wid & 3;

    const int K = HID;
    const int NCH = K / BKH;  // 32
    const __half* Wh = (PHASE == 1)
        ? d_w1h + (size_t)e * N1 * HID
        : d_w2h + (size_t)e * HID * INT_DIM;

    // ---- cp.async assignments ----
    const __half* aSrc[4]; bool aval[4]; uint32_t aDst[4];
    #pragma unroll
    for (int i = 0; i < 4; i++) {
        int chunk = i * 512 + tid;
        int row = chunk >> 3, c16 = chunk & 7;
        int rg = rt + row;
        aval[i] = rg < cnt;
        aDst[i] = (uint32_t)(row * (LDS_H * 2) + c16 * 16);
        if (PHASE == 1) {
            int tok = aval[i] ? (d_row_slot[off + rg] >> 1) : 0;
            aSrc[i] = d_hid16 + (size_t)tok * HID + c16 * 8;
        } else {
            aSrc[i] = d_act16 + (size_t)(off + (aval[i] ? rg : 0)) * INT_DIM + c16 * 8;
        }
    }
    const __half* bSrc[2]; uint32_t bDst[2];
    #pragma unroll
    for (int i = 0; i < 2; i++) {
        int chunk = i * 512 + tid;
        int row = chunk >> 3, c16 = chunk & 7;
        int grow;
        if (PHASE == 1) grow = (row < 64) ? (nt + row) : (INT_DIM + nt + (row - 64));
        else            grow = nt + row;
        bDst[i] = (uint32_t)(B_OFF + row * (LDS_H * 2) + c16 * 16);
        bSrc[i] = Wh + (size_t)grow * K + c16 * 8;
    }

    // ldmatrix byte offsets (kk = 0)
    int aOff[4], bOff[2];
    #pragma unroll
    for (int mi = 0; mi < 4; mi++)
        aOff[mi] = ((wm * 64 + mi * 16 + (lane & 15)) * LDS_H) * 2 + (lane >> 4) * 16;
    #pragma unroll
    for (int g = 0; g < 2; g++)
        bOff[g] = B_OFF + ((wn * 32 + g * 16 + ((lane >> 4) & 1) * 8 + (lane & 7)) * LDS_H) * 2
                  + ((lane >> 3) & 1) * 16;

    float acc[4][4][4];
    #pragma unroll
    for (int mi = 0; mi < 4; mi++)
        #pragma unroll
        for (int ni = 0; ni < 4; ni++)
            #pragma unroll
            for (int q = 0; q < 4; q++) acc[mi][ni][q] = 0.f;

    #define ISSUE(ks) do {                                              \
        uint32_t _base = sb + ((ks) % NSTAGE) * STAGE_BYTES;            \
        int _ko = (ks) * BKH;                                           \
        _Pragma("unroll")                                               \
        for (int _i = 0; _i < 4; _i++)                                  \
            cp16(_base + aDst[_i], aSrc[_i] + _ko, aval[_i]);           \
        _Pragma("unroll")                                               \
        for (int _i = 0; _i < 2; _i++)                                  \
            cp16(_base + bDst[_i], bSrc[_i] + _ko, true);               \
        CP_COMMIT();                                                    \
    } while (0)

    ISSUE(0);
    ISSUE(1);
    ISSUE(2);

    for (int c = 0; c < NCH; c++) {
        CP_WAIT(2);
        __syncthreads();
        if (c + 3 < NCH) ISSUE(c + 3); else CP_COMMIT();

        const uint32_t st = sb + (c % NSTAGE) * STAGE_BYTES;
        #pragma unroll
        for (int kk = 0; kk < 4; kk++) {
            const int kb = kk * 32;
            uint32_t a[4][4], b[4][2];
            #pragma unroll
            for (int mi = 0; mi < 4; mi++)
                ldsm4(a[mi][0], a[mi][1], a[mi][2], a[mi][3], st + aOff[mi] + kb);
            #pragma unroll
            for (int g = 0; g < 2; g++)
                ldsm4(b[2 * g][0], b[2 * g][1], b[2 * g + 1][0], b[2 * g + 1][1],
                      st + bOff[g] + kb);
            #pragma unroll
            for (int mi = 0; mi < 4; mi++)
                #pragma unroll
                for (int ni = 0; ni < 4; ni++)
                    mma16816(acc[mi][ni][0], acc[mi][ni][1], acc[mi][ni][2], acc[mi][ni][3],
                             a[mi][0], a[mi][1], a[mi][2], a[mi][3],
                             b[ni][0], b[ni][1]);
        }
    }
    #undef ISSUE
    CP_WAIT(0);
    __syncthreads();  // all reads done before smem reuse in epilogue

    // ---- epilogue ----
    if (PHASE == 1) {
        float* exch = (float*)smem_raw;  // 256 x 66 fp32 = 67584 <= SMEM_DYN
        const int EP = 66;
        if (wn < 2) {
            #pragma unroll
            for (int mi = 0; mi < 4; mi++) {
                int row0 = wm * 64 + mi * 16 + (lane >> 2);
                #pragma unroll
                for (int ni = 0; ni < 4; ni++) {
                    int col = wn * 32 + ni * 8 + 2 * (lane & 3);
                    float g0 = acc[mi][ni][0], g1 = acc[mi][ni][1];
                    float g2 = acc[mi][ni][2], g3 = acc[mi][ni][3];
                    exch[row0 * EP + col]           = g0 / (1.f + __expf(-g0));
                    exch[row0 * EP + col + 1]       = g1 / (1.f + __expf(-g1));
                    exch[(row0 + 8) * EP + col]     = g2 / (1.f + __expf(-g2));
                    exch[(row0 + 8) * EP + col + 1] = g3 / (1.f + __expf(-g3));
                }
            }
        }
        __syncthreads();
        if (wn >= 2) {
            #pragma unroll
            for (int mi = 0; mi < 4; mi++) {
                int row0 = wm * 64 + mi * 16 + (lane >> 2);
                int rg0 = rt + row0, rg1 = rg0 + 8;
                bool v0 = rg0 < cnt, v1 = rg1 < cnt;
                float w0 = v0 ? wts[d_row_slot[off + rg0]] : 0.f;
                float w1 = v1 ? wts[d_row_slot[off + rg1]] : 0.f;
                #pragma unroll
                for (int ni = 0; ni < 4; ni++) {
                    int col = (wn - 2) * 32 + ni * 8 + 2 * (lane & 3);
                    float s0 = exch[row0 * EP + col];
                    float s1 = exch[row0 * EP + col + 1];
                    float s2 = exch[(row0 + 8) * EP + col];
                    float s3 = exch[(row0 + 8) * EP + col + 1];
                    float a0 = s0 * acc[mi][ni][0] * w0;
                    float a1 = s1 * acc[mi][ni][1] * w0;
                    float a2 = s2 * acc[mi][ni][2] * w1;
                    float a3 = s3 * acc[mi][ni][3] * w1;
                    if (v0) {
                        __half2 h = __floats2half2_rn(a0, a1);
                        *(uint32_t*)&d_act16[(size_t)(off + rg0) * INT_DIM + nt + col] =
                            *(uint32_t*)&h;
                    }
                    if (v1) {
                        __half2 h = __floats2half2_rn(a2, a3);
                        *(uint32_t*)&d_act16[(size_t)(off + rg1) * INT_DIM + nt + col] =
                            *(uint32_t*)&h;
                    }
                }
            }
        }
    } else {
        // atomicAdd weighted (weights pre-applied in act) rows into out[token]
        #pragma unroll
        for (int mi = 0; mi < 4; mi++) {
            int row0 = wm * 64 + mi * 16 + (lane >> 2);
            int rg0 = rt + row0, rg1 = rg0 + 8;
            bool v0 = rg0 < cnt, v1 = rg1 < cnt;
            int t0 = v0 ? (d_row_slot[off + rg0] >> 1) : 0;
            int t1 = v1 ? (d_row_slot[off + rg1] >> 1) : 0;
            #pragma unroll
            for (int ni = 0; ni < 4; ni++) {
                int col = nt + wn * 32 + ni * 8 + 2 * (lane & 3);
                if (v0) {
                    float* p = out + (size_t)t0 * HID + col;
                    atomicAdd(p,     acc[mi][ni][0]);
                    atomicAdd(p + 1, acc[mi][ni][1]);
                }
                if (v1) {
                    float* p = out + (size_t)t1 * HID + col;
                    atomicAdd(p,     acc[mi][ni][2]);
                    atomicAdd(p + 1, acc[mi][ni][3]);
                }
            }
        }
    }
}

// ---------------- launcher ----------------
extern "C" void kernel_launch(void* const* d_in, const int* in_sizes, int n_in,
                              void* d_out, int out_size) {
    const float* hidden = (const float*)d_in[0];
    const int*   topk   = (const int*)  d_in[1];
    const float* wts    = (const float*)d_in[2];
    const float* gup    = (const float*)d_in[3];
    const float* downW  = (const float*)d_in[4];
    float* out = (float*)d_out;

    cudaFuncSetAttribute(moe_mma<1>, cudaFuncAttributeMaxDynamicSharedMemorySize, SMEM_DYN);
    cudaFuncSetAttribute(moe_mma<2>, cudaFuncAttributeMaxDynamicSharedMemorySize, SMEM_DYN);

    __half* hid16p; cudaGetSymbolAddress((void**)&hid16p, d_hid16);
    __half* w1p;    cudaGetSymbolAddress((void**)&w1p,    d_w1h);
    __half* w2p;    cudaGetSymbolAddress((void**)&w2p,    d_w2h);

    route_kernel<<<1, 256>>>(topk);
    {
        int n4h = NTOK * HID / 4;
        cvt_kernel<<<1184, 256>>>(hidden, hid16p, n4h);
        int n41 = NE * N1 * HID / 4;
        cvt_kernel<<<4736, 256>>>(gup, w1p, n41);
        int n42 = NE * HID * INT_DIM / 4;
        cvt_kernel<<<4736, 256>>>(downW, w2p, n42);
    }
    zero_kernel<<<1184, 256>>>(out, NTOK * HID / 4);
    moe_mma<1><<<dim3(INT_DIM / 64, TK / BLKM, NE), 512, SMEM_DYN>>>(wts, out);
    moe_mma<2><<<dim3(HID / 128, TK / BLKM, NE), 512, SMEM_DYN>>>(wts, out);
}